// round 7
// baseline (speedup 1.0000x reference)
#include <cuda_runtime.h>

#define B_ 1024
#define T_ 256
#define H_ 512
#define S_ 64

// h ping-pong scratch (static device memory; no allocations anywhere)
__device__ __align__(16) float g_hbuf[2][B_ * H_];

// ---- packed f32x2 helpers (2x fp32 FMA throughput on sm_103a) ----
__device__ __forceinline__ unsigned long long pk2(float a, float b) {
    unsigned long long r;
    asm("mov.b64 %0, {%1, %2};" : "=l"(r) : "f"(a), "f"(b));
    return r;
}
__device__ __forceinline__ float2 up2(unsigned long long v) {
    float2 r;
    asm("mov.b64 {%0, %1}, %2;" : "=f"(r.x), "=f"(r.y) : "l"(v));
    return r;
}
#define FFMA2(d, a, b, c) \
    asm("fma.rn.f32x2 %0, %1, %2, %3;" : "=l"(d) : "l"(a), "l"(b), "l"(c))

// Step 0: h = relu(x[:,0] * w_in + bias), starting from h == 0.
__global__ void rnn_first(const float* __restrict__ x, const float* __restrict__ w_in,
                          const float* __restrict__ b_ih, const float* __restrict__ b_hh) {
    int idx = blockIdx.x * 256 + threadIdx.x;   // 0 .. B*H-1
    int b = idx >> 9;
    int i = idx & (H_ - 1);
    float v = x[b * T_] * w_in[i] + b_ih[i] + b_hh[i];
    g_hbuf[0][idx] = fmaxf(v, 0.0f);
}

// One recurrence step: hout = relu(xv * w_in + hin @ W^T + bias).
// R=false (warmup): xv = x[b, t].
// R=true (rollout): xv = y_b = hin[b,:] . w_fc + b_fc (fused into the K-loop,
//                   computed by every CTA since every tile needs y as its input),
//                   y written by the in0==0 CTA column.
// Grid (16,16): CTA tile 64(b) x 32(i), 256 threads, per-thread 4b x 2i held
// as f32x2 b-pairs. W chunk stored in smem as duplicated (w,w) pairs so the
// inner loop is pure LDS.128 + FFMA2 (no packing MOVs).
template <bool R>
__global__ __launch_bounds__(256) void rnn_step(
    int ping,
    const float* __restrict__ W,        // H x H row-major (W_hh)
    const float* __restrict__ w_in,     // H   (W_ih is (H,1) contiguous)
    const float* __restrict__ b_ih,
    const float* __restrict__ b_hh,
    const float* __restrict__ x, int t, // warmup input column
    const float* __restrict__ w_fc,     // H   (W_fc is (1,H) contiguous)
    const float* __restrict__ b_fc,
    float* __restrict__ yout, int s)    // rollout output
{
    // rows padded to 68 floats: keeps 16B alignment (272B row) and breaks
    // store-side bank conflicts (stride 64 would alias all rows to one bank set)
    __shared__ __align__(16) float As[2][16][68];  // A chunk, [k][b]
    __shared__ __align__(16) float Ws[2][16][68];  // W chunk, [k][2*i+d] duplicated pairs
    __shared__ float swfc[H_];

    const float* hin  = g_hbuf[ping];
    float*       hout = g_hbuf[ping ^ 1];

    const int tid = threadIdx.x;
    const int bm0 = blockIdx.x * 64;
    const int in0 = blockIdx.y * 32;

    // A loader: 64 rows x 16 k per chunk; thread -> (row, 4 k)
    const int arow = tid >> 2;          // 0..63
    const int aq   = tid & 3;           // 0..3
    const float* Ap = hin + (bm0 + arow) * H_ + aq * 4;

    // W loader: 32 rows x 16 k per chunk; thread -> (row, 2 k)
    const int wrow = tid >> 3;          // 0..31
    const int wq   = tid & 7;           // 0..7
    const float* Wp = W + (in0 + wrow) * H_ + wq * 2;

    if (R) { swfc[tid] = w_fc[tid]; swfc[tid + 256] = w_fc[tid + 256]; }

    // chunk 0 -> buffer 0
    float4 va = *(const float4*)Ap;
    float2 vw = *(const float2*)Wp;
    As[0][aq * 4 + 0][arow] = va.x; As[0][aq * 4 + 1][arow] = va.y;
    As[0][aq * 4 + 2][arow] = va.z; As[0][aq * 4 + 3][arow] = va.w;
    *(float2*)&Ws[0][wq * 2 + 0][2 * wrow] = make_float2(vw.x, vw.x);
    *(float2*)&Ws[0][wq * 2 + 1][2 * wrow] = make_float2(vw.y, vw.y);
    __syncthreads();

    // compute-side indices: 16 b-groups x 16 i-groups
    const int bl  = (tid & 15) * 4;     // local b base: 4 rows = 2 f32x2 pairs
    const int ig2 = tid >> 4;           // i-group: 2 cols -> one dup-pair 16B read

    unsigned long long acc00 = 0, acc01 = 0, acc10 = 0, acc11 = 0;
    unsigned long long yac0 = 0, yac1 = 0;

    for (int kc = 0; kc < 32; ++kc) {
        const int cur = kc & 1;
        if (kc < 31) {  // register prefetch of next chunk (hides L2 latency)
            va = *(const float4*)(Ap + (kc + 1) * 16);
            vw = *(const float2*)(Wp + (kc + 1) * 16);
        }
        const float (*Ac)[68] = As[cur];
        const float (*Wc)[68] = Ws[cur];
#pragma unroll
        for (int j = 0; j < 16; ++j) {
            ulonglong2 a2 = *(const ulonglong2*)&Ac[j][bl];       // 4 b = 2 pairs
            ulonglong2 w2 = *(const ulonglong2*)&Wc[j][4 * ig2];  // 2 dup w-pairs
            FFMA2(acc00, a2.x, w2.x, acc00);
            FFMA2(acc10, a2.y, w2.x, acc10);
            FFMA2(acc01, a2.x, w2.y, acc01);
            FFMA2(acc11, a2.y, w2.y, acc11);
            if (R) {
                float wf = swfc[kc * 16 + j];
                unsigned long long wfp = pk2(wf, wf);
                FFMA2(yac0, a2.x, wfp, yac0);
                FFMA2(yac1, a2.y, wfp, yac1);
            }
        }
        if (kc < 31) {
            const int nb = cur ^ 1;
            As[nb][aq * 4 + 0][arow] = va.x; As[nb][aq * 4 + 1][arow] = va.y;
            As[nb][aq * 4 + 2][arow] = va.z; As[nb][aq * 4 + 3][arow] = va.w;
            *(float2*)&Ws[nb][wq * 2 + 0][2 * wrow] = make_float2(vw.x, vw.x);
            *(float2*)&Ws[nb][wq * 2 + 1][2 * wrow] = make_float2(vw.y, vw.y);
        }
        __syncthreads();
    }

    const int bg = bm0 + bl;
    const int ig = in0 + 2 * ig2;

    // unpack: fa[r][c] for (b = bg+r, i = ig+c)
    float fa[4][2];
    { float2 u = up2(acc00); fa[0][0] = u.x; fa[1][0] = u.y; }
    { float2 u = up2(acc10); fa[2][0] = u.x; fa[3][0] = u.y; }
    { float2 u = up2(acc01); fa[0][1] = u.x; fa[1][1] = u.y; }
    { float2 u = up2(acc11); fa[2][1] = u.x; fa[3][1] = u.y; }

    float xv[4];
    if (R) {
        float bfc = b_fc[0];
        float2 y0 = up2(yac0);
        float2 y1 = up2(yac1);
        xv[0] = y0.x + bfc; xv[1] = y0.y + bfc;
        xv[2] = y1.x + bfc; xv[3] = y1.y + bfc;
        // identical FMA order everywhere -> deterministic; one writer column
        if (in0 == 0 && ig2 == 0) {
#pragma unroll
            for (int r = 0; r < 4; ++r) yout[(bg + r) * S_ + s] = xv[r];
        }
    } else {
#pragma unroll
        for (int r = 0; r < 4; ++r) xv[r] = x[(bg + r) * T_ + t];
    }

    float2 wi = *(const float2*)(w_in + ig);
    float2 bi = *(const float2*)(b_ih + ig);
    float2 bh = *(const float2*)(b_hh + ig);
    float bvx = bi.x + bh.x, bvy = bi.y + bh.y;

#pragma unroll
    for (int r = 0; r < 4; ++r) {
        float2 hv;
        hv.x = fmaxf(fa[r][0] + xv[r] * wi.x + bvx, 0.0f);
        hv.y = fmaxf(fa[r][1] + xv[r] * wi.y + bvy, 0.0f);
        *(float2*)(hout + (bg + r) * H_ + ig) = hv;
    }
}

extern "C" void kernel_launch(void* const* d_in, const int* in_sizes, int n_in,
                              void* d_out, int out_size) {
    // metadata order: x, W_ih, W_hh, b_ih, b_hh, W_fc, b_fc, num_steps
    const float* x    = (const float*)d_in[0];
    const float* W_ih = (const float*)d_in[1];   // (H,1) -> H contiguous = w_in
    const float* W_hh = (const float*)d_in[2];   // (H,H)
    const float* b_ih = (const float*)d_in[3];
    const float* b_hh = (const float*)d_in[4];
    const float* W_fc = (const float*)d_in[5];   // (1,H) -> H contiguous
    const float* b_fc = (const float*)d_in[6];
    float* out = (float*)d_out;                  // (B, 64, 1) float32
    (void)in_sizes; (void)n_in; (void)out_size;  // num_steps fixed at 64

    // t = 0 (h starts at zero)
    rnn_first<<<(B_ * H_) / 256, 256>>>(x, W_ih, b_ih, b_hh);

    dim3 grid(16, 16);  // 256 CTAs of 64x32 -> 2 CTAs co-resident on most SMs
    int ping = 0;       // rnn_first wrote g_hbuf[0]

    // warmup t = 1 .. 255
    for (int t = 1; t < T_; ++t) {
        rnn_step<false><<<grid, 256>>>(ping, W_hh, W_ih, b_ih, b_hh,
                                       x, t, nullptr, nullptr, nullptr, 0);
        ping ^= 1;
    }
    // rollout s = 0 .. 63 (y fused into the step kernel)
    for (int s = 0; s < S_; ++s) {
        rnn_step<true><<<grid, 256>>>(ping, W_hh, W_ih, b_ih, b_hh,
                                      nullptr, 0, W_fc, b_fc, out, s);
        ping ^= 1;
    }
}

// round 12
// speedup vs baseline: 1.5658x; 1.5658x over previous
#include <cuda_runtime.h>

#define B_ 1024
#define T_ 256
#define H_ 512
#define S_ 64

// h ping-pong scratch, TRANSPOSED: h[i][b]  (static device memory; no allocs)
__device__ __align__(16) float g_hbuf[2][H_ * B_];
// W_hh transposed: Wt[k][i] = W_hh[i][k]
__device__ __align__(16) float g_Wt[H_ * H_];

// ---- packed f32x2 helpers (2x fp32 FMA throughput on sm_103a) ----
__device__ __forceinline__ unsigned long long pk2(float a, float b) {
    unsigned long long r;
    asm("mov.b64 %0, {%1, %2};" : "=l"(r) : "f"(a), "f"(b));
    return r;
}
__device__ __forceinline__ float2 up2(unsigned long long v) {
    float2 r;
    asm("mov.b64 {%0, %1}, %2;" : "=f"(r.x), "=f"(r.y) : "l"(v));
    return r;
}
#define FFMA2(d, a, b, c) \
    asm("fma.rn.f32x2 %0, %1, %2, %3;" : "=l"(d) : "l"(a), "l"(b), "l"(c))

// One-shot: Wt[k][i] = W_hh[i][k]
__global__ void transpose_W(const float* __restrict__ W) {
    __shared__ float t[32][33];
    int bx = blockIdx.x * 32, by = blockIdx.y * 32;
    int x = threadIdx.x, y = threadIdx.y;   // block (32, 8)
#pragma unroll
    for (int r = 0; r < 32; r += 8)
        t[y + r][x] = W[(by + y + r) * H_ + bx + x];
    __syncthreads();
#pragma unroll
    for (int r = 0; r < 32; r += 8)
        g_Wt[(bx + y + r) * H_ + by + x] = t[x][y + r];
}

// Step 0: h[i][b] = relu(x[b,0] * w_in[i] + bias[i]), h starts at zero.
__global__ void rnn_first(const float* __restrict__ x, const float* __restrict__ w_in,
                          const float* __restrict__ b_ih, const float* __restrict__ b_hh) {
    int idx = blockIdx.x * 256 + threadIdx.x;   // 0 .. H*B-1, i-major
    int i = idx >> 10;
    int b = idx & (B_ - 1);
    float v = x[b * T_] * w_in[i] + b_ih[i] + b_hh[i];
    g_hbuf[0][idx] = fmaxf(v, 0.0f);
}

// One recurrence step on transposed h: hout[i][b] = relu(xv_b*w_in[i] + sum_k hin[k][b]*Wt[k][i] + bias[i]).
// R=false: xv_b = x[b, t].  R=true: xv_b = y_b = sum_k hin[k][b]*w_fc[k] + b_fc (fused; written once).
// Grid (32,8): CTA tile 32b x 64i, 128 threads (4 warps), per-thread 4b x 4i,
// accumulators packed f32x2 along b.
template <bool R>
__global__ __launch_bounds__(128) void rnn_step(
    int ping,
    const float* __restrict__ w_in,
    const float* __restrict__ b_ih,
    const float* __restrict__ b_hh,
    const float* __restrict__ x, int t,
    const float* __restrict__ w_fc,
    const float* __restrict__ b_fc,
    float* __restrict__ yout, int s)
{
    __shared__ __align__(16) float As[2][32][36];   // A chunk [k][b], natural from hin
    __shared__ __align__(16) float Ws[2][32][68];   // W chunk [k][i], natural from g_Wt
    __shared__ float swfc[H_];

    const float* hin  = g_hbuf[ping];
    float*       hout = g_hbuf[ping ^ 1];

    const int tid = threadIdx.x;
    const int bm0 = blockIdx.x * 32;
    const int in0 = blockIdx.y * 64;

    // loader mapping (both natural, float4, no transpose in smem)
    const int lk = tid >> 2;            // 0..31 : k row within chunk
    const int ab = (tid & 3) * 8;       // A col offset (8 floats)
    const int wi = (tid & 3) * 16;      // W col offset (16 floats)
    const float* Ap = hin  + lk * B_ + bm0 + ab;
    const float* Wp = g_Wt + lk * H_ + in0 + wi;

    if (R) {
        swfc[tid]       = w_fc[tid];
        swfc[tid + 128] = w_fc[tid + 128];
        swfc[tid + 256] = w_fc[tid + 256];
        swfc[tid + 384] = w_fc[tid + 384];
    }

    // chunk 0 -> buffer 0
    float4 va0 = *(const float4*)Ap;
    float4 va1 = *(const float4*)(Ap + 4);
    float4 vw0 = *(const float4*)Wp;
    float4 vw1 = *(const float4*)(Wp + 4);
    float4 vw2 = *(const float4*)(Wp + 8);
    float4 vw3 = *(const float4*)(Wp + 12);
    *(float4*)&As[0][lk][ab]      = va0;
    *(float4*)&As[0][lk][ab + 4]  = va1;
    *(float4*)&Ws[0][lk][wi]      = vw0;
    *(float4*)&Ws[0][lk][wi + 4]  = vw1;
    *(float4*)&Ws[0][lk][wi + 8]  = vw2;
    *(float4*)&Ws[0][lk][wi + 12] = vw3;
    __syncthreads();

    // compute mapping: warp covers 32b x 16i; lane = 8 b-groups x 4 i-groups
    const int lane = tid & 31;
    const int wid  = tid >> 5;          // 0..3
    const int bl   = (lane & 7) * 4;    // local b base (4 b = 2 f32x2 pairs)
    const int il   = wid * 16 + (lane >> 3) * 4;  // local i base (4 i)

    unsigned long long acc[2][4];
#pragma unroll
    for (int p = 0; p < 2; ++p)
#pragma unroll
        for (int c = 0; c < 4; ++c) acc[p][c] = 0ull;
    unsigned long long yac[2] = {0ull, 0ull};

    for (int kc = 0; kc < 16; ++kc) {
        const int cur = kc & 1;
        if (kc < 15) {  // register prefetch of next chunk (L2-resident)
            const float* Apn = Ap + (kc + 1) * 32 * B_;
            const float* Wpn = Wp + (kc + 1) * 32 * H_;
            va0 = *(const float4*)Apn;
            va1 = *(const float4*)(Apn + 4);
            vw0 = *(const float4*)Wpn;
            vw1 = *(const float4*)(Wpn + 4);
            vw2 = *(const float4*)(Wpn + 8);
            vw3 = *(const float4*)(Wpn + 12);
        }
        const float (*Ac)[36] = As[cur];
        const float (*Wc)[68] = Ws[cur];
#pragma unroll
        for (int j = 0; j < 32; ++j) {
            ulonglong2 a2 = *(const ulonglong2*)&Ac[j][bl];   // 4 b = 2 pairs (128B/warp unique)
            float4 w4 = *(const float4*)&Wc[j][il];           // 4 w (64B/warp, 8-way bcast)
            unsigned long long wp0 = pk2(w4.x, w4.x), wp1 = pk2(w4.y, w4.y),
                               wp2 = pk2(w4.z, w4.z), wp3 = pk2(w4.w, w4.w);
            FFMA2(acc[0][0], a2.x, wp0, acc[0][0]);
            FFMA2(acc[1][0], a2.y, wp0, acc[1][0]);
            FFMA2(acc[0][1], a2.x, wp1, acc[0][1]);
            FFMA2(acc[1][1], a2.y, wp1, acc[1][1]);
            FFMA2(acc[0][2], a2.x, wp2, acc[0][2]);
            FFMA2(acc[1][2], a2.y, wp2, acc[1][2]);
            FFMA2(acc[0][3], a2.x, wp3, acc[0][3]);
            FFMA2(acc[1][3], a2.y, wp3, acc[1][3]);
            if (R) {
                float wf = swfc[kc * 32 + j];
                unsigned long long wfp = pk2(wf, wf);
                FFMA2(yac[0], a2.x, wfp, yac[0]);
                FFMA2(yac[1], a2.y, wfp, yac[1]);
            }
        }
        if (kc < 15) {
            const int nb = cur ^ 1;
            *(float4*)&As[nb][lk][ab]      = va0;
            *(float4*)&As[nb][lk][ab + 4]  = va1;
            *(float4*)&Ws[nb][lk][wi]      = vw0;
            *(float4*)&Ws[nb][lk][wi + 4]  = vw1;
            *(float4*)&Ws[nb][lk][wi + 8]  = vw2;
            *(float4*)&Ws[nb][lk][wi + 12] = vw3;
        }
        __syncthreads();
    }

    const int bg = bm0 + bl;
    const int ig = in0 + il;

    // unpack: fa[r][c] for (b = bg+r, i = ig+c)
    float fa[4][4];
#pragma unroll
    for (int p = 0; p < 2; ++p)
#pragma unroll
        for (int c = 0; c < 4; ++c) {
            float2 u = up2(acc[p][c]);
            fa[2 * p][c]     = u.x;
            fa[2 * p + 1][c] = u.y;
        }

    float xv[4];
    if (R) {
        float bfc = b_fc[0];
        float2 y0 = up2(yac[0]);
        float2 y1 = up2(yac[1]);
        xv[0] = y0.x + bfc; xv[1] = y0.y + bfc;
        xv[2] = y1.x + bfc; xv[3] = y1.y + bfc;
        // yac is bitwise identical for every thread sharing a b-range -> one writer set
        if (blockIdx.y == 0 && wid == 0 && (lane >> 3) == 0) {
#pragma unroll
            for (int r = 0; r < 4; ++r) yout[(bg + r) * S_ + s] = xv[r];
        }
    } else {
#pragma unroll
        for (int r = 0; r < 4; ++r) xv[r] = x[(bg + r) * T_ + t];
    }

    float4 wi4 = *(const float4*)(w_in + ig);
    float4 bi4 = *(const float4*)(b_ih + ig);
    float4 bh4 = *(const float4*)(b_hh + ig);
    float wv[4] = {wi4.x, wi4.y, wi4.z, wi4.w};
    float bv[4] = {bi4.x + bh4.x, bi4.y + bh4.y, bi4.z + bh4.z, bi4.w + bh4.w};

    // write transposed hout[i][b]: one float4 (4 consecutive b) per i
#pragma unroll
    for (int c = 0; c < 4; ++c) {
        float4 hv;
        hv.x = fmaxf(fa[0][c] + xv[0] * wv[c] + bv[c], 0.0f);
        hv.y = fmaxf(fa[1][c] + xv[1] * wv[c] + bv[c], 0.0f);
        hv.z = fmaxf(fa[2][c] + xv[2] * wv[c] + bv[c], 0.0f);
        hv.w = fmaxf(fa[3][c] + xv[3] * wv[c] + bv[c], 0.0f);
        *(float4*)(hout + (ig + c) * B_ + bg) = hv;
    }
}

extern "C" void kernel_launch(void* const* d_in, const int* in_sizes, int n_in,
                              void* d_out, int out_size) {
    // metadata order: x, W_ih, W_hh, b_ih, b_hh, W_fc, b_fc, num_steps
    const float* x    = (const float*)d_in[0];
    const float* W_ih = (const float*)d_in[1];   // (H,1) -> H contiguous = w_in
    const float* W_hh = (const float*)d_in[2];   // (H,H)
    const float* b_ih = (const float*)d_in[3];
    const float* b_hh = (const float*)d_in[4];
    const float* W_fc = (const float*)d_in[5];   // (1,H) -> H contiguous
    const float* b_fc = (const float*)d_in[6];
    float* out = (float*)d_out;                  // (B, 64, 1) float32
    (void)in_sizes; (void)n_in; (void)out_size;  // num_steps fixed at 64

    transpose_W<<<dim3(16, 16), dim3(32, 8)>>>(W_hh);
    rnn_first<<<(H_ * B_) / 256, 256>>>(x, W_ih, b_ih, b_hh);

    dim3 grid(32, 8);   // 256 CTAs of 128 threads -> 2 CTAs/SM on most SMs
    int ping = 0;       // rnn_first wrote g_hbuf[0]

    for (int t = 1; t < T_; ++t) {
        rnn_step<false><<<grid, 128>>>(ping, W_ih, b_ih, b_hh,
                                       x, t, nullptr, nullptr, nullptr, 0);
        ping ^= 1;
    }
    for (int s = 0; s < S_; ++s) {
        rnn_step<true><<<grid, 128>>>(ping, W_ih, b_ih, b_hh,
                                      nullptr, 0, W_fc, b_fc, out, s);
        ping ^= 1;
    }
}

// round 15
// speedup vs baseline: 2.2685x; 1.4488x over previous
#include <cuda_runtime.h>
#include <cuda_bf16.h>
#include <cstdint>

#define B_ 1024
#define T_ 256
#define H_ 512
#define S_ 64
#define KTOT 1536
#define NCH 24          // 1536 / 64 K-chunks

// Acat = [Ahi | Alo | Ahi], Wcat = [Whi | Whi | Wlo]  (bf16, K contiguous)
__device__ __align__(16) __nv_bfloat16 g_A[2][B_ * KTOT];   // ping-pong state
__device__ __align__(16) __nv_bfloat16 g_W[H_ * KTOT];
__device__ float g_y[B_];

__device__ __forceinline__ uint32_t smem_u32(const void* p) {
    uint32_t a;
    asm("{ .reg .u64 t; cvta.to.shared.u64 t, %1; cvt.u32.u64 %0, t; }" : "=r"(a) : "l"(p));
    return a;
}

#define LDSM4(r0, r1, r2, r3, addr)                                            \
    asm volatile("ldmatrix.sync.aligned.m8n8.x4.shared.b16 {%0,%1,%2,%3}, [%4];" \
                 : "=r"(r0), "=r"(r1), "=r"(r2), "=r"(r3) : "r"(addr))

#define MMA16816(c, a0, a1, a2, a3, b0, b1)                                    \
    asm volatile("mma.sync.aligned.m16n8k16.row.col.f32.bf16.bf16.f32 "        \
                 "{%0,%1,%2,%3},{%4,%5,%6,%7},{%8,%9},{%0,%1,%2,%3};"          \
                 : "+f"((c)[0]), "+f"((c)[1]), "+f"((c)[2]), "+f"((c)[3])      \
                 : "r"(a0), "r"(a1), "r"(a2), "r"(a3), "r"(b0), "r"(b1))

// ---------------- prep kernels ----------------
__global__ void wsplit(const float* __restrict__ W) {
    int idx = blockIdx.x * 256 + threadIdx.x;    // n*512 + k
    int n = idx >> 9, k = idx & 511;
    float v = W[idx];
    __nv_bfloat16 h = __float2bfloat16(v);
    __nv_bfloat16 l = __float2bfloat16(v - __bfloat162float(h));
    __nv_bfloat16* p = g_W + n * KTOT;
    p[k] = h; p[512 + k] = h; p[1024 + k] = l;
}

__global__ void rnn_first(const float* __restrict__ x, const float* __restrict__ w_in,
                          const float* __restrict__ b_ih, const float* __restrict__ b_hh) {
    int idx = blockIdx.x * 256 + threadIdx.x;    // b*512 + i
    int b = idx >> 9, i = idx & 511;
    float v = fmaxf(x[b * T_] * w_in[i] + b_ih[i] + b_hh[i], 0.0f);
    __nv_bfloat16 h = __float2bfloat16(v);
    __nv_bfloat16 l = __float2bfloat16(v - __bfloat162float(h));
    __nv_bfloat16* p = g_A[0] + b * KTOT;
    p[i] = h; p[512 + i] = l; p[1024 + i] = h;
}

// y[b] = h[b,:].w_fc + b_fc ; h = hi + lo. One warp per batch row.
__global__ void ykern(int ping, const float* __restrict__ w_fc, const float* __restrict__ b_fc,
                      float* __restrict__ out, int s) {
    int w = blockIdx.x * 8 + (threadIdx.x >> 5);
    int lane = threadIdx.x & 31;
    const __nv_bfloat16* p = g_A[ping] + w * KTOT;
    float acc = 0.0f;
#pragma unroll
    for (int k = lane; k < 512; k += 32)
        acc += (__bfloat162float(p[k]) + __bfloat162float(p[512 + k])) * w_fc[k];
#pragma unroll
    for (int o = 16; o; o >>= 1) acc += __shfl_xor_sync(0xFFFFFFFFu, acc, o);
    if (lane == 0) {
        float y = acc + b_fc[0];
        g_y[w] = y;
        out[w * S_ + s] = y;
    }
}

// ---------------- tensor-core step kernel ----------------
// Grid (16,8): CTA tile 64(b) x 64(i); 4 warps, warp tile 32x32.
// C = Acat @ Wcat^T (K=1536) in fp32 accum, then fused bias/x/relu/re-split.
template <bool R>
__global__ __launch_bounds__(128) void rnn_step(
    int ping, const float* __restrict__ w_in, const float* __restrict__ b_ih,
    const float* __restrict__ b_hh, const float* __restrict__ x, int t)
{
    // 72-halfword row pad: 144B stride -> 16B/row rotation -> conflict-free ldmatrix
    __shared__ __align__(16) __nv_bfloat16 As[2][64][72];
    __shared__ __align__(16) __nv_bfloat16 Ws[2][64][72];
    __shared__ float s_w[64], s_b[64];

    const int tid = threadIdx.x;
    const int lane = tid & 31, w = tid >> 5;
    const int wm = w & 1, wn = w >> 1;
    const int m0 = blockIdx.x * 64, n0 = blockIdx.y * 64;

    if (tid < 64) {
        s_w[tid] = w_in[n0 + tid];
        s_b[tid] = b_ih[n0 + tid] + b_hh[n0 + tid];
    }

    const uint4* gA = reinterpret_cast<const uint4*>(g_A[ping]);
    const uint4* gW = reinterpret_cast<const uint4*>(g_W);   // row stride 192 uint4

    // loader mapping: 512 uint4 per tile / 128 threads = 4 each
    uint4 pva[4], pvw[4];
#pragma unroll
    for (int q = 0; q < 4; ++q) {
        int idx = tid + q * 128, r = idx >> 3, u = idx & 7;
        pva[q] = gA[(m0 + r) * 192 + u];
        pvw[q] = gW[(n0 + r) * 192 + u];
    }
#pragma unroll
    for (int q = 0; q < 4; ++q) {
        int idx = tid + q * 128, r = idx >> 3, u = idx & 7;
        *(uint4*)&As[0][r][u * 8] = pva[q];
        *(uint4*)&Ws[0][r][u * 8] = pvw[q];
    }
    __syncthreads();

    float acc[2][4][4];
#pragma unroll
    for (int a = 0; a < 2; ++a)
#pragma unroll
        for (int b = 0; b < 4; ++b)
#pragma unroll
            for (int c = 0; c < 4; ++c) acc[a][b][c] = 0.0f;

    const uint32_t sA = smem_u32(As), sW = smem_u32(Ws);
    // A frag addr: rows m = wm*32 + mt*16 + (lane&15); col halves by lane>>4
    const uint32_t aoff = ((wm * 32 + (lane & 15)) * 72 + (lane >> 4) * 8) * 2;
    // B frag addr: rows n = wn*32 + nt*16 + ((lane>>4)<<3) + (lane&7); col k-half by (lane>>3)&1
    const uint32_t boff = ((wn * 32 + ((lane >> 4) << 3) + (lane & 7)) * 72 + ((lane >> 3) & 1) * 8) * 2;

    for (int c = 0; c < NCH; ++c) {
        const int cur = c & 1;
        if (c < NCH - 1) {
#pragma unroll
            for (int q = 0; q < 4; ++q) {
                int idx = tid + q * 128, r = idx >> 3, u = idx & 7;
                pva[q] = gA[(m0 + r) * 192 + (c + 1) * 8 + u];
                pvw[q] = gW[(n0 + r) * 192 + (c + 1) * 8 + u];
            }
        }
        const uint32_t ab = sA + cur * 9216 + aoff;
        const uint32_t bb = sW + cur * 9216 + boff;
#pragma unroll
        for (int kk = 0; kk < 4; ++kk) {
            uint32_t af[2][4], bf[2][4];
            LDSM4(af[0][0], af[0][1], af[0][2], af[0][3], ab + kk * 32);
            LDSM4(af[1][0], af[1][1], af[1][2], af[1][3], ab + kk * 32 + 2304);
            LDSM4(bf[0][0], bf[0][1], bf[0][2], bf[0][3], bb + kk * 32);
            LDSM4(bf[1][0], bf[1][1], bf[1][2], bf[1][3], bb + kk * 32 + 2304);
#pragma unroll
            for (int mt = 0; mt < 2; ++mt)
#pragma unroll
                for (int nt = 0; nt < 2; ++nt) {
                    MMA16816(acc[mt][nt * 2 + 0], af[mt][0], af[mt][1], af[mt][2], af[mt][3],
                             bf[nt][0], bf[nt][1]);
                    MMA16816(acc[mt][nt * 2 + 1], af[mt][0], af[mt][1], af[mt][2], af[mt][3],
                             bf[nt][2], bf[nt][3]);
                }
        }
        if (c < NCH - 1) {
            const int nb = cur ^ 1;
#pragma unroll
            for (int q = 0; q < 4; ++q) {
                int idx = tid + q * 128, r = idx >> 3, u = idx & 7;
                *(uint4*)&As[nb][r][u * 8] = pva[q];
                *(uint4*)&Ws[nb][r][u * 8] = pvw[q];
            }
        }
        __syncthreads();
    }

    // epilogue: c-frag (r, 2c),(r,2c+1),(r+8,2c),(r+8,2c+1) per m16n8 tile
    const int rb = lane >> 2;
    float xv[2][2];
#pragma unroll
    for (int mt = 0; mt < 2; ++mt) {
        int r0 = m0 + wm * 32 + mt * 16 + rb;
        if (R) { xv[mt][0] = g_y[r0]; xv[mt][1] = g_y[r0 + 8]; }
        else   { xv[mt][0] = x[r0 * T_ + t]; xv[mt][1] = x[(r0 + 8) * T_ + t]; }
    }

    __nv_bfloat16* outA = g_A[ping ^ 1];
#pragma unroll
    for (int mt = 0; mt < 2; ++mt)
#pragma unroll
        for (int nq = 0; nq < 4; ++nq) {
            const int iloc = wn * 32 + nq * 8 + 2 * (lane & 3);
            const int gi = n0 + iloc;
            const float w0 = s_w[iloc], w1 = s_w[iloc + 1];
            const float bb0 = s_b[iloc], bb1 = s_b[iloc + 1];
#pragma unroll
            for (int hh = 0; hh < 2; ++hh) {
                float v0 = fmaxf(acc[mt][nq][hh * 2 + 0] + xv[mt][hh] * w0 + bb0, 0.0f);
                float v1 = fmaxf(acc[mt][nq][hh * 2 + 1] + xv[mt][hh] * w1 + bb1, 0.0f);
                __nv_bfloat16 h0 = __float2bfloat16(v0), h1 = __float2bfloat16(v1);
                __nv_bfloat16 l0 = __float2bfloat16(v0 - __bfloat162float(h0));
                __nv_bfloat16 l1 = __float2bfloat16(v1 - __bfloat162float(h1));
                __nv_bfloat162 hp; hp.x = h0; hp.y = h1;
                __nv_bfloat162 lp; lp.x = l0; lp.y = l1;
                uint32_t hu = *(uint32_t*)&hp, lu = *(uint32_t*)&lp;
                const int b = m0 + wm * 32 + mt * 16 + rb + hh * 8;
                __nv_bfloat16* p = outA + b * KTOT;
                *(uint32_t*)(p + gi)        = hu;   // Ahi
                *(uint32_t*)(p + 512 + gi)  = lu;   // Alo
                *(uint32_t*)(p + 1024 + gi) = hu;   // Ahi duplicate
            }
        }
}

// ---------------- launch ----------------
extern "C" void kernel_launch(void* const* d_in, const int* in_sizes, int n_in,
                              void* d_out, int out_size) {
    // metadata order: x, W_ih, W_hh, b_ih, b_hh, W_fc, b_fc, num_steps
    const float* x    = (const float*)d_in[0];
    const float* W_ih = (const float*)d_in[1];   // (H,1) contiguous = w_in
    const float* W_hh = (const float*)d_in[2];
    const float* b_ih = (const float*)d_in[3];
    const float* b_hh = (const float*)d_in[4];
    const float* W_fc = (const float*)d_in[5];   // (1,H) contiguous
    const float* b_fc = (const float*)d_in[6];
    float* out = (float*)d_out;                  // (B, 64, 1) float32
    (void)in_sizes; (void)n_in; (void)out_size;

    wsplit<<<(H_ * H_) / 256, 256>>>(W_hh);
    rnn_first<<<(B_ * H_) / 256, 256>>>(x, W_ih, b_ih, b_hh);

    dim3 grid(16, 8);   // 128 CTAs, 64x64 tiles
    int ping = 0;
    for (int t = 1; t < T_; ++t) {
        rnn_step<false><<<grid, 128>>>(ping, W_ih, b_ih, b_hh, x, t);
        ping ^= 1;
    }
    for (int s = 0; s < S_; ++s) {
        ykern<<<128, 256>>>(ping, W_fc, b_fc, out, s);
        if (s < S_ - 1) {   // final h update is unused by the reference
            rnn_step<true><<<grid, 128>>>(ping, W_ih, b_ih, b_hh, nullptr, 0);
            ping ^= 1;
        }
    }
}

// round 16
// speedup vs baseline: 2.7722x; 1.2220x over previous
#include <cuda_runtime.h>
#include <cuda_bf16.h>
#include <cstdint>

#define B_ 1024
#define T_ 256
#define H_ 512
#define S_ 64
#define KTOT 1536
#define NCH 24          // 1536 / 64 K-chunks
#define NSTG 4          // cp.async pipeline stages
#define STG_BYTES 18432 // (64*72 + 64*72) bf16 = 9216 + 9216

// Acat = [Ahi | Alo | Ahi], Wcat = [Whi | Whi | Wlo]  (bf16, K contiguous)
// => C = Ahi@Whi + Alo@Whi + Ahi@Wlo in fp32 accum (drops only lo*lo ~2^-18)
__device__ __align__(16) __nv_bfloat16 g_A[2][B_ * KTOT];   // ping-pong state
__device__ __align__(16) __nv_bfloat16 g_W[H_ * KTOT];
__device__ float g_y[B_];

__device__ __forceinline__ uint32_t smem_u32(const void* p) {
    uint32_t a;
    asm("{ .reg .u64 t; cvta.to.shared.u64 t, %1; cvt.u32.u64 %0, t; }" : "=r"(a) : "l"(p));
    return a;
}

#define CP_ASYNC16(smem, gptr) \
    asm volatile("cp.async.cg.shared.global [%0], [%1], 16;" :: "r"(smem), "l"(gptr))
#define CP_COMMIT() asm volatile("cp.async.commit_group;" ::: "memory")
#define CP_WAIT2()  asm volatile("cp.async.wait_group 2;" ::: "memory")
#define CP_WAIT0()  asm volatile("cp.async.wait_group 0;" ::: "memory")

#define LDSM4(r0, r1, r2, r3, addr)                                            \
    asm volatile("ldmatrix.sync.aligned.m8n8.x4.shared.b16 {%0,%1,%2,%3}, [%4];" \
                 : "=r"(r0), "=r"(r1), "=r"(r2), "=r"(r3) : "r"(addr))

#define MMA16816(c, a0, a1, a2, a3, b0, b1)                                    \
    asm volatile("mma.sync.aligned.m16n8k16.row.col.f32.bf16.bf16.f32 "        \
                 "{%0,%1,%2,%3},{%4,%5,%6,%7},{%8,%9},{%0,%1,%2,%3};"          \
                 : "+f"((c)[0]), "+f"((c)[1]), "+f"((c)[2]), "+f"((c)[3])      \
                 : "r"(a0), "r"(a1), "r"(a2), "r"(a3), "r"(b0), "r"(b1))

// ---------------- prep kernels ----------------
__global__ void wsplit(const float* __restrict__ W) {
    int idx = blockIdx.x * 256 + threadIdx.x;    // n*512 + k
    int n = idx >> 9, k = idx & 511;
    float v = W[idx];
    __nv_bfloat16 h = __float2bfloat16(v);
    __nv_bfloat16 l = __float2bfloat16(v - __bfloat162float(h));
    __nv_bfloat16* p = g_W + n * KTOT;
    p[k] = h; p[512 + k] = h; p[1024 + k] = l;
}

__global__ void rnn_first(const float* __restrict__ x, const float* __restrict__ w_in,
                          const float* __restrict__ b_ih, const float* __restrict__ b_hh) {
    int idx = blockIdx.x * 256 + threadIdx.x;    // b*512 + i
    int b = idx >> 9, i = idx & 511;
    float v = fmaxf(x[b * T_] * w_in[i] + b_ih[i] + b_hh[i], 0.0f);
    __nv_bfloat16 h = __float2bfloat16(v);
    __nv_bfloat16 l = __float2bfloat16(v - __bfloat162float(h));
    __nv_bfloat16* p = g_A[0] + b * KTOT;
    p[i] = h; p[512 + i] = l; p[1024 + i] = h;
}

// y[b] = h[b,:].w_fc + b_fc ; h = hi + lo. One warp per batch row.
__global__ void ykern(int ping, const float* __restrict__ w_fc, const float* __restrict__ b_fc,
                      float* __restrict__ out, int s) {
    int w = blockIdx.x * 8 + (threadIdx.x >> 5);
    int lane = threadIdx.x & 31;
    const __nv_bfloat16* p = g_A[ping] + w * KTOT;
    float acc = 0.0f;
#pragma unroll
    for (int k = lane; k < 512; k += 32)
        acc += (__bfloat162float(p[k]) + __bfloat162float(p[512 + k])) * w_fc[k];
#pragma unroll
    for (int o = 16; o; o >>= 1) acc += __shfl_xor_sync(0xFFFFFFFFu, acc, o);
    if (lane == 0) {
        float y = acc + b_fc[0];
        g_y[w] = y;
        out[w * S_ + s] = y;
    }
}

// ---------------- tensor-core step kernel ----------------
// Grid (16,8): CTA tile 64(b) x 64(i); 256 threads / 8 warps, warp tile 32x16.
// 4-stage cp.async pipeline, K=1536 in chunks of 64.
template <bool R>
__global__ __launch_bounds__(256) void rnn_step(
    int ping, const float* __restrict__ w_in, const float* __restrict__ b_ih,
    const float* __restrict__ b_hh, const float* __restrict__ x, int t)
{
    extern __shared__ char sm[];                 // NSTG * STG_BYTES
    __shared__ float s_w[64], s_b[64];

    const int tid = threadIdx.x;
    const int lane = tid & 31, w = tid >> 5;
    const int wm = w & 1;          // m half (32 rows)
    const int wn = w >> 1;         // n quarter (16 cols)
    const int m0 = blockIdx.x * 64, n0 = blockIdx.y * 64;

    if (tid < 64) {
        s_w[tid] = w_in[n0 + tid];
        s_b[tid] = b_ih[n0 + tid] + b_hh[n0 + tid];
    }

    const char* gA = (const char*)(g_A[ping]) ;
    const char* gW = (const char*)g_W;
    const uint32_t smb = smem_u32(sm);

    // loader: per stage, A = 512 x 16B (64 rows x 8 units), W same; 2 each/thread
    const int lr = tid >> 3, lu = tid & 7;       // covers idx = tid and tid+256
    const int lr2 = (tid + 256) >> 3;
    // gmem row stride = 3072 bytes (1536 bf16)
    const char* gAp  = gA + (long)(m0 + lr)  * 3072 + lu * 16;
    const char* gAp2 = gA + (long)(m0 + lr2) * 3072 + lu * 16;
    const char* gWp  = gW + (long)(n0 + lr)  * 3072 + lu * 16;
    const char* gWp2 = gW + (long)(n0 + lr2) * 3072 + lu * 16;
    const uint32_t sA1 = smb + lr * 144 + lu * 16;
    const uint32_t sA2 = smb + lr2 * 144 + lu * 16;
    const uint32_t sW1 = sA1 + 9216, sW2 = sA2 + 9216;

    // prologue: stages 0..2
#pragma unroll
    for (int s = 0; s < 3; ++s) {
        const uint32_t so = s * STG_BYTES;
        const int go = s * 128;                  // chunk s -> byte offset s*8*16
        CP_ASYNC16(sA1 + so, gAp + go);
        CP_ASYNC16(sA2 + so, gAp2 + go);
        CP_ASYNC16(sW1 + so, gWp + go);
        CP_ASYNC16(sW2 + so, gWp2 + go);
        CP_COMMIT();
    }

    float acc[2][2][4];
#pragma unroll
    for (int a = 0; a < 2; ++a)
#pragma unroll
        for (int b = 0; b < 2; ++b)
#pragma unroll
            for (int c = 0; c < 4; ++c) acc[a][b][c] = 0.0f;

    // fragment addresses (verified maps from R15, re-based for 32x16 warp tile)
    const uint32_t aoff = ((wm * 32 + (lane & 15)) * 72 + (lane >> 4) * 8) * 2;
    const uint32_t boff = 9216 +
        ((wn * 16 + ((lane >> 4) << 3) + (lane & 7)) * 72 + ((lane >> 3) & 1) * 8) * 2;

    for (int c = 0; c < NCH; ++c) {
        CP_WAIT2();
        __syncthreads();
        const uint32_t sb = (c & 3) * STG_BYTES;
        // issue loads for chunk c+3 into stage (c+3)&3 (read-complete since last barrier)
        if (c + 3 < NCH) {
            const uint32_t so = ((c + 3) & 3) * STG_BYTES;
            const int go = (c + 3) * 128;
            CP_ASYNC16(sA1 + so, gAp + go);
            CP_ASYNC16(sA2 + so, gAp2 + go);
            CP_ASYNC16(sW1 + so, gWp + go);
            CP_ASYNC16(sW2 + so, gWp2 + go);
        }
        CP_COMMIT();

        const uint32_t ab = smb + sb + aoff;
        const uint32_t bb = smb + sb + boff;
#pragma unroll
        for (int kk = 0; kk < 4; ++kk) {
            uint32_t af[2][4], bf[4];
            LDSM4(af[0][0], af[0][1], af[0][2], af[0][3], ab + kk * 32);
            LDSM4(af[1][0], af[1][1], af[1][2], af[1][3], ab + kk * 32 + 2304);
            LDSM4(bf[0], bf[1], bf[2], bf[3], bb + kk * 32);
#pragma unroll
            for (int mt = 0; mt < 2; ++mt) {
                MMA16816(acc[mt][0], af[mt][0], af[mt][1], af[mt][2], af[mt][3], bf[0], bf[1]);
                MMA16816(acc[mt][1], af[mt][0], af[mt][1], af[mt][2], af[mt][3], bf[2], bf[3]);
            }
        }
        __syncthreads();
    }
    CP_WAIT0();

    // epilogue: c-frag rows rb, rb+8; cols 2*(lane&3), +1 within each n8 tile
    const int rb = lane >> 2;
    float xv[2][2];
#pragma unroll
    for (int mt = 0; mt < 2; ++mt) {
        int r0 = m0 + wm * 32 + mt * 16 + rb;
        if (R) { xv[mt][0] = g_y[r0]; xv[mt][1] = g_y[r0 + 8]; }
        else   { xv[mt][0] = x[r0 * T_ + t]; xv[mt][1] = x[(r0 + 8) * T_ + t]; }
    }

    __nv_bfloat16* outA = g_A[ping ^ 1];
#pragma unroll
    for (int mt = 0; mt < 2; ++mt)
#pragma unroll
        for (int nq = 0; nq < 2; ++nq) {
            const int iloc = wn * 16 + nq * 8 + 2 * (lane & 3);
            const int gi = n0 + iloc;
            const float w0 = s_w[iloc], w1 = s_w[iloc + 1];
            const float bb0 = s_b[iloc], bb1 = s_b[iloc + 1];
#pragma unroll
            for (int hh = 0; hh < 2; ++hh) {
                float v0 = fmaxf(acc[mt][nq][hh * 2 + 0] + xv[mt][hh] * w0 + bb0, 0.0f);
                float v1 = fmaxf(acc[mt][nq][hh * 2 + 1] + xv[mt][hh] * w1 + bb1, 0.0f);
                __nv_bfloat16 h0 = __float2bfloat16(v0), h1 = __float2bfloat16(v1);
                __nv_bfloat16 l0 = __float2bfloat16(v0 - __bfloat162float(h0));
                __nv_bfloat16 l1 = __float2bfloat16(v1 - __bfloat162float(h1));
                __nv_bfloat162 hp; hp.x = h0; hp.y = h1;
                __nv_bfloat162 lp; lp.x = l0; lp.y = l1;
                uint32_t hu = *(uint32_t*)&hp, lu2 = *(uint32_t*)&lp;
                const int b = m0 + wm * 32 + mt * 16 + rb + hh * 8;
                __nv_bfloat16* p = outA + b * KTOT;
                *(uint32_t*)(p + gi)        = hu;    // Ahi
                *(uint32_t*)(p + 512 + gi)  = lu2;   // Alo
                *(uint32_t*)(p + 1024 + gi) = hu;    // Ahi duplicate
            }
        }
}

// ---------------- launch ----------------
extern "C" void kernel_launch(void* const* d_in, const int* in_sizes, int n_in,
                              void* d_out, int out_size) {
    // metadata order: x, W_ih, W_hh, b_ih, b_hh, W_fc, b_fc, num_steps
    const float* x    = (const float*)d_in[0];
    const float* W_ih = (const float*)d_in[1];   // (H,1) contiguous = w_in
    const float* W_hh = (const float*)d_in[2];
    const float* b_ih = (const float*)d_in[3];
    const float* b_hh = (const float*)d_in[4];
    const float* W_fc = (const float*)d_in[5];   // (1,H) contiguous
    const float* b_fc = (const float*)d_in[6];
    float* out = (float*)d_out;                  // (B, 64, 1) float32
    (void)in_sizes; (void)n_in; (void)out_size;

    const int smem = NSTG * STG_BYTES;           // 73728
    cudaFuncSetAttribute(rnn_step<false>, cudaFuncAttributeMaxDynamicSharedMemorySize, smem);
    cudaFuncSetAttribute(rnn_step<true>,  cudaFuncAttributeMaxDynamicSharedMemorySize, smem);

    wsplit<<<(H_ * H_) / 256, 256>>>(W_hh);
    rnn_first<<<(B_ * H_) / 256, 256>>>(x, W_ih, b_ih, b_hh);

    dim3 grid(16, 8);   // 128 CTAs, 64x64 tiles
    int ping = 0;
    for (int t = 1; t < T_; ++t) {
        rnn_step<false><<<grid, 256, smem>>>(ping, W_ih, b_ih, b_hh, x, t);
        ping ^= 1;
    }
    for (int s = 0; s < S_; ++s) {
        ykern<<<128, 256>>>(ping, W_fc, b_fc, out, s);
        if (s < S_ - 1) {   // final h update is unused by the reference
            rnn_step<true><<<grid, 256, smem>>>(ping, W_ih, b_ih, b_hh, nullptr, 0);
            ping ^= 1;
        }
    }
}